// round 2
// baseline (speedup 1.0000x reference)
#include <cuda_runtime.h>
#include <cstdint>

#define NB 256
#define NS 32
#define NV 10000
#define DEMB 512
#define DHID 1024
#define DIMG 2048
#define BOS_TOK 1
#define EOS_TOK 2

// ---------------- device scratch (static, no allocations) ----------------
__device__ float g_h0[NB * DHID];
__device__ float g_h1[NB * DHID];
__device__ float g_x [NB * DEMB];          // relu(emb[token]) for current step
__device__ float g_G1[NB * 3 * DHID];      // x @ w_ih^T
__device__ float g_G2[NB * 3 * DHID];      // h @ w_hh^T
__device__ float g_WbT[DHID * DIMG];       // W_b transposed -> [DHID][DIMG]
__device__ unsigned long long g_amax[NB];  // packed (value,index) argmax per row
__device__ int g_tok[NS * NB];

__device__ __forceinline__ float* sbuf(int sel) {
    switch (sel) {
        case 0: return g_h0;
        case 1: return g_h1;
        case 2: return g_x;
        case 3: return g_G1;
        case 4: return g_G2;
        default: return g_WbT;
    }
}

// ---------------- f32x2 helpers (FFMA2: 2x fp32 FMA throughput) ----------------
__device__ __forceinline__ unsigned long long dup2(float a) {
    unsigned long long r;
    asm("mov.b64 %0, {%1, %1};" : "=l"(r) : "f"(a));
    return r;
}
__device__ __forceinline__ void ffma2(unsigned long long& d, unsigned long long a, unsigned long long b) {
    asm("fma.rn.f32x2 %0, %1, %2, %0;" : "+l"(d) : "l"(a), "l"(b));
}
__device__ __forceinline__ float lo32(unsigned long long v) {
    return __uint_as_float((unsigned)(v & 0xFFFFFFFFull));
}
__device__ __forceinline__ float hi32(unsigned long long v) {
    return __uint_as_float((unsigned)(v >> 32));
}

// order-preserving (float,index) pack; max => max value, ties => smallest index
__device__ __forceinline__ unsigned long long packmax(float v, int idx) {
    unsigned int b = __float_as_uint(v);
    b = (b & 0x80000000u) ? ~b : (b | 0x80000000u);
    return ((unsigned long long)b << 32) | (unsigned long long)(0xFFFFFFFFu - (unsigned)idx);
}

// ---------------- W_b transpose: [DIMG][DHID] -> [DHID][DIMG] ----------------
__global__ void transpose_wb(const float* __restrict__ Wb) {
    __shared__ float t[32][33];
    int k0 = blockIdx.x * 32;
    int n0 = blockIdx.y * 32;
    for (int i = threadIdx.y; i < 32; i += 8)
        t[i][threadIdx.x] = Wb[(size_t)(k0 + i) * DHID + n0 + threadIdx.x];
    __syncthreads();
    for (int i = threadIdx.y; i < 32; i += 8)
        g_WbT[(size_t)(n0 + i) * DIMG + k0 + threadIdx.x] = t[threadIdx.x][i];
}

// ---------------- zero the one-hot output ----------------
__global__ void zero_out(float4* o, long long n4) {
    long long i = (long long)blockIdx.x * blockDim.x + threadIdx.x;
    if (i < n4) o[i] = make_float4(0.f, 0.f, 0.f, 0.f);
}

// ---------------- init: x0 = relu(emb[BOS]), amax reset ----------------
__global__ void init_kernel(const float* __restrict__ emb) {
    int b = blockIdx.x;
    if (threadIdx.x == 0) g_amax[b] = 0ull;
    for (int k = threadIdx.x; k < DEMB; k += 128)
        g_x[b * DEMB + k] = fmaxf(emb[(size_t)BOS_TOK * DEMB + k], 0.f);
}

// ---------------- generic 64x128 GEMM (C = A[M,K] * B[N,K]^T), dual dispatch over z ----------------
// Used for h0 (z count 1) and the two gate GEMMs fused in one launch (z count 2).
__global__ __launch_bounds__(256, 2)
void gemm64_dual(int a0, const float* __restrict__ A0e, int b0, const float* __restrict__ B0e, int c0, int K0,
                 int a1, const float* __restrict__ A1e, int b1, const float* __restrict__ B1e, int c1, int K1,
                 int N)
{
    const int z = blockIdx.z;
    const float* A  = z ? ((a1 >= 0) ? sbuf(a1) : A1e) : ((a0 >= 0) ? sbuf(a0) : A0e);
    const float* Bm = z ? ((b1 >= 0) ? sbuf(b1) : B1e) : ((b0 >= 0) ? sbuf(b0) : B0e);
    float* C = sbuf(z ? c1 : c0);
    const int K = z ? K1 : K0;

    __shared__ float As[2][16][72];
    __shared__ float Bs[2][16][128];

    const int tid = threadIdx.x;
    const int tx8 = (tid & 15) * 8;
    const int ty4 = (tid >> 4) * 4;
    const int bm = blockIdx.y * 64;
    const int bn = blockIdx.x * 128;

    const int row = tid >> 2;        // 0..63
    const int kq  = (tid & 3) * 4;   // 0,4,8,12

    const float* Ag  = A  + (size_t)(bm + row) * K + kq;
    const float* Bg0 = Bm + (size_t)(bn + row) * K + kq;
    const float* Bg1 = Bg0 + (size_t)64 * K;

    unsigned long long acc[4][4];
#pragma unroll
    for (int i = 0; i < 4; i++)
#pragma unroll
        for (int p = 0; p < 4; p++) acc[i][p] = 0ull;

    float4 ra, rb0, rb1;
    auto LD = [&](int kt) {
        ra  = *(const float4*)(Ag  + kt * 16);
        rb0 = *(const float4*)(Bg0 + kt * 16);
        rb1 = *(const float4*)(Bg1 + kt * 16);
    };
    auto ST = [&](int buf) {
        As[buf][kq + 0][row] = ra.x;  As[buf][kq + 1][row] = ra.y;
        As[buf][kq + 2][row] = ra.z;  As[buf][kq + 3][row] = ra.w;
        Bs[buf][kq + 0][row] = rb0.x; Bs[buf][kq + 1][row] = rb0.y;
        Bs[buf][kq + 2][row] = rb0.z; Bs[buf][kq + 3][row] = rb0.w;
        Bs[buf][kq + 0][row + 64] = rb1.x; Bs[buf][kq + 1][row + 64] = rb1.y;
        Bs[buf][kq + 2][row + 64] = rb1.z; Bs[buf][kq + 3][row + 64] = rb1.w;
    };

    LD(0); ST(0);
    __syncthreads();
    const int KT = K >> 4;
    int cur = 0;
    for (int kt = 0; kt < KT; ++kt) {
        if (kt + 1 < KT) LD(kt + 1);
#pragma unroll
        for (int k = 0; k < 16; ++k) {
            float4 a = *(const float4*)&As[cur][k][ty4];
            ulonglong2 blo = *(const ulonglong2*)&Bs[cur][k][tx8];
            ulonglong2 bhi = *(const ulonglong2*)&Bs[cur][k][tx8 + 4];
            unsigned long long ad[4] = {dup2(a.x), dup2(a.y), dup2(a.z), dup2(a.w)};
            unsigned long long bd[4] = {blo.x, blo.y, bhi.x, bhi.y};
#pragma unroll
            for (int i = 0; i < 4; i++)
#pragma unroll
                for (int p = 0; p < 4; p++)
                    ffma2(acc[i][p], ad[i], bd[p]);
        }
        if (kt + 1 < KT) ST(cur ^ 1);
        __syncthreads();
        cur ^= 1;
    }

#pragma unroll
    for (int i = 0; i < 4; i++) {
        float* crow = C + (size_t)(bm + ty4 + i) * N + bn + tx8;
#pragma unroll
        for (int p = 0; p < 4; p++) {
            crow[2 * p]     = lo32(acc[i][p]);
            crow[2 * p + 1] = hi32(acc[i][p]);
        }
    }
}

// ---------------- GRU elementwise: h_new from G1, G2, biases, h_old ----------------
__global__ void gru_elem(const float* __restrict__ b_ih, const float* __restrict__ b_hh,
                         int hOldSel, int hNewSel)
{
    int idx = blockIdx.x * blockDim.x + threadIdx.x;   // NB*DHID
    int m = idx >> 10;
    int j = idx & 1023;
    const float* G1 = g_G1 + (size_t)m * (3 * DHID);
    const float* G2 = g_G2 + (size_t)m * (3 * DHID);
    float ir = G1[j]            + b_ih[j];
    float iz = G1[DHID + j]     + b_ih[DHID + j];
    float in_ = G1[2 * DHID + j] + b_ih[2 * DHID + j];
    float hr = G2[j]            + b_hh[j];
    float hz = G2[DHID + j]     + b_hh[DHID + j];
    float hn = G2[2 * DHID + j] + b_hh[2 * DHID + j];
    float r = 1.f / (1.f + expf(-(ir + hr)));
    float z = 1.f / (1.f + expf(-(iz + hz)));
    float n = tanhf(in_ + r * hn);
    float ho = sbuf(hOldSel)[idx];
    sbuf(hNewSel)[idx] = (1.f - z) * n + z * ho;
}

// ---------------- logits GEMM (128x128 tile) fused with +bias +gumbel + argmax ----------------
__global__ __launch_bounds__(256, 2)
void gemm_logits(int aSel, const float* __restrict__ W, const float* __restrict__ bout,
                 const float* __restrict__ gumbel, int step)
{
    const int N = NV, K = DHID;
    const float* A = sbuf(aSel);

    __shared__ float As[2][16][136];
    __shared__ float Bs[2][16][128];
    __shared__ unsigned long long rowmax[128];
    __shared__ float bo[128];

    const int tid = threadIdx.x;
    const int tx8 = (tid & 15) * 8;
    const int ty8 = (tid >> 4) * 8;
    const int bm = blockIdx.y * 128;
    const int bn = blockIdx.x * 128;

    const int row = tid >> 2;        // 0..63
    const int kq  = (tid & 3) * 4;

    const float* Ag0 = A + (size_t)(bm + row) * K + kq;
    const float* Ag1 = Ag0 + (size_t)64 * K;
    const int brow0 = bn + row;
    const int brow1 = brow0 + 64;
    const float* Bg0 = W + (size_t)brow0 * K + kq;
    const float* Bg1 = W + (size_t)brow1 * K + kq;

    unsigned long long acc[8][4];
#pragma unroll
    for (int i = 0; i < 8; i++)
#pragma unroll
        for (int p = 0; p < 4; p++) acc[i][p] = 0ull;

    float4 ra0, ra1, rb0, rb1;
    const float4 f4z = make_float4(0.f, 0.f, 0.f, 0.f);
    auto LD = [&](int kt) {
        ra0 = *(const float4*)(Ag0 + kt * 16);
        ra1 = *(const float4*)(Ag1 + kt * 16);
        rb0 = (brow0 < N) ? *(const float4*)(Bg0 + kt * 16) : f4z;
        rb1 = (brow1 < N) ? *(const float4*)(Bg1 + kt * 16) : f4z;
    };
    auto ST = [&](int buf) {
        As[buf][kq + 0][row] = ra0.x; As[buf][kq + 1][row] = ra0.y;
        As[buf][kq + 2][row] = ra0.z; As[buf][kq + 3][row] = ra0.w;
        As[buf][kq + 0][row + 64] = ra1.x; As[buf][kq + 1][row + 64] = ra1.y;
        As[buf][kq + 2][row + 64] = ra1.z; As[buf][kq + 3][row + 64] = ra1.w;
        Bs[buf][kq + 0][row] = rb0.x; Bs[buf][kq + 1][row] = rb0.y;
        Bs[buf][kq + 2][row] = rb0.z; Bs[buf][kq + 3][row] = rb0.w;
        Bs[buf][kq + 0][row + 64] = rb1.x; Bs[buf][kq + 1][row + 64] = rb1.y;
        Bs[buf][kq + 2][row + 64] = rb1.z; Bs[buf][kq + 3][row + 64] = rb1.w;
    };

    LD(0); ST(0);
    __syncthreads();
    const int KT = K >> 4;   // 64
    int cur = 0;
    for (int kt = 0; kt < KT; ++kt) {
        if (kt + 1 < KT) LD(kt + 1);
#pragma unroll
        for (int k = 0; k < 16; ++k) {
            float4 a0 = *(const float4*)&As[cur][k][ty8];
            float4 a1 = *(const float4*)&As[cur][k][ty8 + 4];
            ulonglong2 blo = *(const ulonglong2*)&Bs[cur][k][tx8];
            ulonglong2 bhi = *(const ulonglong2*)&Bs[cur][k][tx8 + 4];
            unsigned long long ad[8] = {dup2(a0.x), dup2(a0.y), dup2(a0.z), dup2(a0.w),
                                        dup2(a1.x), dup2(a1.y), dup2(a1.z), dup2(a1.w)};
            unsigned long long bd[4] = {blo.x, blo.y, bhi.x, bhi.y};
#pragma unroll
            for (int i = 0; i < 8; i++)
#pragma unroll
                for (int p = 0; p < 4; p++)
                    ffma2(acc[i][p], ad[i], bd[p]);
        }
        if (kt + 1 < KT) ST(cur ^ 1);
        __syncthreads();
        cur ^= 1;
    }

    // epilogue: + b_out + gumbel, block argmax, global atomic merge
    if (tid < 128) {
        rowmax[tid] = 0ull;
        int n = bn + tid;
        bo[tid] = (n < N) ? bout[n] : 0.f;
    }
    __syncthreads();

#pragma unroll
    for (int i = 0; i < 8; i++) {
        int m = bm + ty8 + i;
        const float* grow = gumbel + ((size_t)step * NB + m) * (size_t)NV + bn;
        unsigned long long best = 0ull;
#pragma unroll
        for (int p = 0; p < 4; p++) {
            int nl = tx8 + 2 * p;
            int n = bn + nl;
            if (n + 1 < N) {
                float2 g = *(const float2*)(grow + nl);
                float v0 = lo32(acc[i][p]) + bo[nl] + g.x;
                float v1 = hi32(acc[i][p]) + bo[nl + 1] + g.y;
                unsigned long long p0 = packmax(v0, n);
                unsigned long long p1 = packmax(v1, n + 1);
                unsigned long long pm = p0 > p1 ? p0 : p1;
                if (pm > best) best = pm;
            } else if (n < N) {
                float v0 = lo32(acc[i][p]) + bo[nl] + grow[nl];
                unsigned long long p0 = packmax(v0, n);
                if (p0 > best) best = p0;
            }
        }
        atomicMax(&rowmax[ty8 + i], best);
    }
    __syncthreads();
    if (tid < 128 && rowmax[tid])
        atomicMax(&g_amax[bm + tid], rowmax[tid]);
}

// ---------------- finalize step: decode argmax, write one-hot, gather next x ----------------
__global__ void finalize_kernel(const float* __restrict__ emb, float* __restrict__ out, int s) {
    int b = blockIdx.x;
    __shared__ int stok;
    if (threadIdx.x == 0) {
        unsigned long long p = g_amax[b];
        int t = (int)(0xFFFFFFFFu - (unsigned)(p & 0xFFFFFFFFull));
        stok = t;
        g_tok[s * NB + b] = t;
        g_amax[b] = 0ull;
        out[((size_t)b * NS + s) * NV + t] = 1.0f;
    }
    __syncthreads();
    int t = stok;
    for (int k = threadIdx.x; k < DEMB; k += 128)
        g_x[b * DEMB + k] = fmaxf(emb[(size_t)t * DEMB + k], 0.f);
}

// ---------------- msg_lens: last EOS index + 1, else S ----------------
__global__ void lens_kernel(float* __restrict__ out, int out_size) {
    int b = threadIdx.x;
    int len = NS;
    for (int s = NS - 1; s >= 0; --s) {
        if (g_tok[s * NB + b] == EOS_TOK) { len = s + 1; break; }
    }
    if (out_size >= NB * NS * NV + NB)
        out[(size_t)NB * NS * NV + b] = (float)len;
}

// ---------------- launch ----------------
extern "C" void kernel_launch(void* const* d_in, const int* in_sizes, int n_in,
                              void* d_out, int out_size)
{
    const float* image = (const float*)d_in[0];
    const float* W_b   = (const float*)d_in[1];
    const float* emb   = (const float*)d_in[2];
    const float* w_ih  = (const float*)d_in[3];
    const float* w_hh  = (const float*)d_in[4];
    const float* b_ih  = (const float*)d_in[5];
    const float* b_hh  = (const float*)d_in[6];
    const float* W_out = (const float*)d_in[7];
    const float* b_out = (const float*)d_in[8];
    const float* gum   = (const float*)d_in[9];
    float* out = (float*)d_out;

    // zero the one-hot region
    long long n4 = (long long)NB * NS * NV / 4;
    zero_out<<<(unsigned)((n4 + 255) / 256), 256>>>((float4*)out, n4);

    // one-time prep
    transpose_wb<<<dim3(DIMG / 32, DHID / 32), dim3(32, 8)>>>(W_b);
    init_kernel<<<NB, 128>>>(emb);

    // h0 = image @ W_b  (A=image ext, B=g_WbT sel 5, C=g_h0 sel 0)
    gemm64_dual<<<dim3(DHID / 128, NB / 64, 1), 256>>>(
        -1, image, 5, nullptr, 0, DIMG,
        -1, nullptr, -1, nullptr, 0, 0,
        DHID);

    for (int s = 0; s < NS; ++s) {
        int hc = s & 1;       // current h buffer (h0 lives in buf 0)
        int hn = hc ^ 1;      // next h buffer
        // fused gate GEMMs: z=0 -> G1 = x @ w_ih^T (K=512); z=1 -> G2 = h @ w_hh^T (K=1024)
        gemm64_dual<<<dim3(3 * DHID / 128, NB / 64, 2), 256>>>(
            2, nullptr, -1, w_ih, 3, DEMB,
            hc, nullptr, -1, w_hh, 4, DHID,
            3 * DHID);
        gru_elem<<<(NB * DHID) / 256, 256>>>(b_ih, b_hh, hc, hn);
        gemm_logits<<<dim3((NV + 127) / 128, NB / 128), 256>>>(hn, W_out, b_out, gum, s);
        finalize_kernel<<<NB, 128>>>(emb, out, s);
    }

    lens_kernel<<<1, 256>>>(out, out_size);
}

// round 3
// speedup vs baseline: 1.0010x; 1.0010x over previous
#include <cuda_runtime.h>
#include <cstdint>

#define NB 256
#define NS 32
#define NV 10000
#define DEMB 512
#define DHID 1024
#define DIMG 2048
#define BOS_TOK 1
#define EOS_TOK 2

// ---------------- device scratch (static, no allocations) ----------------
__device__ float g_h0[NB * DHID];
__device__ float g_h1[NB * DHID];
__device__ float g_x [NB * DEMB];          // relu(emb[token]) for current step
__device__ float g_G1[NB * 3 * DHID];      // x @ w_ih^T
__device__ float g_G2[NB * 3 * DHID];      // h @ w_hh^T
__device__ float g_WbT[DHID * DIMG];       // W_b transposed -> [DHID][DIMG]
__device__ unsigned long long g_amax[NB];  // packed (value,index) argmax per row
__device__ int g_tok[NS * NB];

__device__ __forceinline__ float* sbuf(int sel) {
    switch (sel) {
        case 0: return g_h0;
        case 1: return g_h1;
        case 2: return g_x;
        case 3: return g_G1;
        case 4: return g_G2;
        default: return g_WbT;
    }
}

// ---------------- f32x2 helpers (FFMA2: 2x fp32 FMA throughput) ----------------
__device__ __forceinline__ unsigned long long dup2(float a) {
    unsigned long long r;
    asm("mov.b64 %0, {%1, %1};" : "=l"(r) : "f"(a));
    return r;
}
__device__ __forceinline__ void ffma2(unsigned long long& d, unsigned long long a, unsigned long long b) {
    asm("fma.rn.f32x2 %0, %1, %2, %0;" : "+l"(d) : "l"(a), "l"(b));
}
__device__ __forceinline__ float lo32(unsigned long long v) {
    return __uint_as_float((unsigned)(v & 0xFFFFFFFFull));
}
__device__ __forceinline__ float hi32(unsigned long long v) {
    return __uint_as_float((unsigned)(v >> 32));
}

// order-preserving (float,index) pack; max => max value, ties => smallest index
__device__ __forceinline__ unsigned long long packmax(float v, int idx) {
    unsigned int b = __float_as_uint(v);
    b = (b & 0x80000000u) ? ~b : (b | 0x80000000u);
    return ((unsigned long long)b << 32) | (unsigned long long)(0xFFFFFFFFu - (unsigned)idx);
}

// ---------------- W_b transpose: [DIMG][DHID] -> [DHID][DIMG] ----------------
__global__ void transpose_wb(const float* __restrict__ Wb) {
    __shared__ float t[32][33];
    int k0 = blockIdx.x * 32;
    int n0 = blockIdx.y * 32;
    for (int i = threadIdx.y; i < 32; i += 8)
        t[i][threadIdx.x] = Wb[(size_t)(k0 + i) * DHID + n0 + threadIdx.x];
    __syncthreads();
    for (int i = threadIdx.y; i < 32; i += 8)
        g_WbT[(size_t)(n0 + i) * DIMG + k0 + threadIdx.x] = t[threadIdx.x][i];
}

// ---------------- zero the one-hot output ----------------
__global__ void zero_out(float4* o, long long n4) {
    long long i = (long long)blockIdx.x * blockDim.x + threadIdx.x;
    if (i < n4) o[i] = make_float4(0.f, 0.f, 0.f, 0.f);
}

// ---------------- init: x0 = relu(emb[BOS]), amax reset ----------------
__global__ void init_kernel(const float* __restrict__ emb) {
    int b = blockIdx.x;
    if (threadIdx.x == 0) g_amax[b] = 0ull;
    for (int k = threadIdx.x; k < DEMB; k += 128)
        g_x[b * DEMB + k] = fmaxf(emb[(size_t)BOS_TOK * DEMB + k], 0.f);
}

// ---------------- generic 64x128 GEMM (C = A[M,K] * B[N,K]^T), dual dispatch over z ----------------
// Used for h0 (z count 1) and the two gate GEMMs fused in one launch (z count 2).
__global__ __launch_bounds__(256, 2)
void gemm64_dual(int a0, const float* __restrict__ A0e, int b0, const float* __restrict__ B0e, int c0, int K0,
                 int a1, const float* __restrict__ A1e, int b1, const float* __restrict__ B1e, int c1, int K1,
                 int N)
{
    const int z = blockIdx.z;
    const float* A  = z ? ((a1 >= 0) ? sbuf(a1) : A1e) : ((a0 >= 0) ? sbuf(a0) : A0e);
    const float* Bm = z ? ((b1 >= 0) ? sbuf(b1) : B1e) : ((b0 >= 0) ? sbuf(b0) : B0e);
    float* C = sbuf(z ? c1 : c0);
    const int K = z ? K1 : K0;

    __shared__ float As[2][16][72];
    __shared__ float Bs[2][16][128];

    const int tid = threadIdx.x;
    const int tx8 = (tid & 15) * 8;
    const int ty4 = (tid >> 4) * 4;
    const int bm = blockIdx.y * 64;
    const int bn = blockIdx.x * 128;

    const int row = tid >> 2;        // 0..63
    const int kq  = (tid & 3) * 4;   // 0,4,8,12

    const float* Ag  = A  + (size_t)(bm + row) * K + kq;
    const float* Bg0 = Bm + (size_t)(bn + row) * K + kq;
    const float* Bg1 = Bg0 + (size_t)64 * K;

    unsigned long long acc[4][4];
#pragma unroll
    for (int i = 0; i < 4; i++)
#pragma unroll
        for (int p = 0; p < 4; p++) acc[i][p] = 0ull;

    float4 ra, rb0, rb1;
    auto LD = [&](int kt) {
        ra  = *(const float4*)(Ag  + kt * 16);
        rb0 = *(const float4*)(Bg0 + kt * 16);
        rb1 = *(const float4*)(Bg1 + kt * 16);
    };
    auto ST = [&](int buf) {
        As[buf][kq + 0][row] = ra.x;  As[buf][kq + 1][row] = ra.y;
        As[buf][kq + 2][row] = ra.z;  As[buf][kq + 3][row] = ra.w;
        Bs[buf][kq + 0][row] = rb0.x; Bs[buf][kq + 1][row] = rb0.y;
        Bs[buf][kq + 2][row] = rb0.z; Bs[buf][kq + 3][row] = rb0.w;
        Bs[buf][kq + 0][row + 64] = rb1.x; Bs[buf][kq + 1][row + 64] = rb1.y;
        Bs[buf][kq + 2][row + 64] = rb1.z; Bs[buf][kq + 3][row + 64] = rb1.w;
    };

    LD(0); ST(0);
    __syncthreads();
    const int KT = K >> 4;
    int cur = 0;
    for (int kt = 0; kt < KT; ++kt) {
        if (kt + 1 < KT) LD(kt + 1);
#pragma unroll
        for (int k = 0; k < 16; ++k) {
            float4 a = *(const float4*)&As[cur][k][ty4];
            ulonglong2 blo = *(const ulonglong2*)&Bs[cur][k][tx8];
            ulonglong2 bhi = *(const ulonglong2*)&Bs[cur][k][tx8 + 4];
            unsigned long long ad[4] = {dup2(a.x), dup2(a.y), dup2(a.z), dup2(a.w)};
            unsigned long long bd[4] = {blo.x, blo.y, bhi.x, bhi.y};
#pragma unroll
            for (int i = 0; i < 4; i++)
#pragma unroll
                for (int p = 0; p < 4; p++)
                    ffma2(acc[i][p], ad[i], bd[p]);
        }
        if (kt + 1 < KT) ST(cur ^ 1);
        __syncthreads();
        cur ^= 1;
    }

#pragma unroll
    for (int i = 0; i < 4; i++) {
        float* crow = C + (size_t)(bm + ty4 + i) * N + bn + tx8;
#pragma unroll
        for (int p = 0; p < 4; p++) {
            crow[2 * p]     = lo32(acc[i][p]);
            crow[2 * p + 1] = hi32(acc[i][p]);
        }
    }
}

// ---------------- GRU elementwise: h_new from G1, G2, biases, h_old ----------------
__global__ void gru_elem(const float* __restrict__ b_ih, const float* __restrict__ b_hh,
                         int hOldSel, int hNewSel)
{
    int idx = blockIdx.x * blockDim.x + threadIdx.x;   // NB*DHID
    int m = idx >> 10;
    int j = idx & 1023;
    const float* G1 = g_G1 + (size_t)m * (3 * DHID);
    const float* G2 = g_G2 + (size_t)m * (3 * DHID);
    float ir = G1[j]            + b_ih[j];
    float iz = G1[DHID + j]     + b_ih[DHID + j];
    float in_ = G1[2 * DHID + j] + b_ih[2 * DHID + j];
    float hr = G2[j]            + b_hh[j];
    float hz = G2[DHID + j]     + b_hh[DHID + j];
    float hn = G2[2 * DHID + j] + b_hh[2 * DHID + j];
    float r = 1.f / (1.f + expf(-(ir + hr)));
    float z = 1.f / (1.f + expf(-(iz + hz)));
    float n = tanhf(in_ + r * hn);
    float ho = sbuf(hOldSel)[idx];
    sbuf(hNewSel)[idx] = (1.f - z) * n + z * ho;
}

// ---------------- logits GEMM (128x128 tile) fused with +bias +gumbel + argmax ----------------
__global__ __launch_bounds__(256, 2)
void gemm_logits(int aSel, const float* __restrict__ W, const float* __restrict__ bout,
                 const float* __restrict__ gumbel, int step)
{
    const int N = NV, K = DHID;
    const float* A = sbuf(aSel);

    __shared__ float As[2][16][136];
    __shared__ float Bs[2][16][128];
    __shared__ unsigned long long rowmax[128];
    __shared__ float bo[128];

    const int tid = threadIdx.x;
    const int tx8 = (tid & 15) * 8;
    const int ty8 = (tid >> 4) * 8;
    const int bm = blockIdx.y * 128;
    const int bn = blockIdx.x * 128;

    const int row = tid >> 2;        // 0..63
    const int kq  = (tid & 3) * 4;

    const float* Ag0 = A + (size_t)(bm + row) * K + kq;
    const float* Ag1 = Ag0 + (size_t)64 * K;
    const int brow0 = bn + row;
    const int brow1 = brow0 + 64;
    const float* Bg0 = W + (size_t)brow0 * K + kq;
    const float* Bg1 = W + (size_t)brow1 * K + kq;

    unsigned long long acc[8][4];
#pragma unroll
    for (int i = 0; i < 8; i++)
#pragma unroll
        for (int p = 0; p < 4; p++) acc[i][p] = 0ull;

    float4 ra0, ra1, rb0, rb1;
    const float4 f4z = make_float4(0.f, 0.f, 0.f, 0.f);
    auto LD = [&](int kt) {
        ra0 = *(const float4*)(Ag0 + kt * 16);
        ra1 = *(const float4*)(Ag1 + kt * 16);
        rb0 = (brow0 < N) ? *(const float4*)(Bg0 + kt * 16) : f4z;
        rb1 = (brow1 < N) ? *(const float4*)(Bg1 + kt * 16) : f4z;
    };
    auto ST = [&](int buf) {
        As[buf][kq + 0][row] = ra0.x; As[buf][kq + 1][row] = ra0.y;
        As[buf][kq + 2][row] = ra0.z; As[buf][kq + 3][row] = ra0.w;
        As[buf][kq + 0][row + 64] = ra1.x; As[buf][kq + 1][row + 64] = ra1.y;
        As[buf][kq + 2][row + 64] = ra1.z; As[buf][kq + 3][row + 64] = ra1.w;
        Bs[buf][kq + 0][row] = rb0.x; Bs[buf][kq + 1][row] = rb0.y;
        Bs[buf][kq + 2][row] = rb0.z; Bs[buf][kq + 3][row] = rb0.w;
        Bs[buf][kq + 0][row + 64] = rb1.x; Bs[buf][kq + 1][row + 64] = rb1.y;
        Bs[buf][kq + 2][row + 64] = rb1.z; Bs[buf][kq + 3][row + 64] = rb1.w;
    };

    LD(0); ST(0);
    __syncthreads();
    const int KT = K >> 4;   // 64
    int cur = 0;
    for (int kt = 0; kt < KT; ++kt) {
        if (kt + 1 < KT) LD(kt + 1);
#pragma unroll
        for (int k = 0; k < 16; ++k) {
            float4 a0 = *(const float4*)&As[cur][k][ty8];
            float4 a1 = *(const float4*)&As[cur][k][ty8 + 4];
            ulonglong2 blo = *(const ulonglong2*)&Bs[cur][k][tx8];
            ulonglong2 bhi = *(const ulonglong2*)&Bs[cur][k][tx8 + 4];
            unsigned long long ad[8] = {dup2(a0.x), dup2(a0.y), dup2(a0.z), dup2(a0.w),
                                        dup2(a1.x), dup2(a1.y), dup2(a1.z), dup2(a1.w)};
            unsigned long long bd[4] = {blo.x, blo.y, bhi.x, bhi.y};
#pragma unroll
            for (int i = 0; i < 8; i++)
#pragma unroll
                for (int p = 0; p < 4; p++)
                    ffma2(acc[i][p], ad[i], bd[p]);
        }
        if (kt + 1 < KT) ST(cur ^ 1);
        __syncthreads();
        cur ^= 1;
    }

    // epilogue: + b_out + gumbel, block argmax, global atomic merge
    if (tid < 128) {
        rowmax[tid] = 0ull;
        int n = bn + tid;
        bo[tid] = (n < N) ? bout[n] : 0.f;
    }
    __syncthreads();

#pragma unroll
    for (int i = 0; i < 8; i++) {
        int m = bm + ty8 + i;
        const float* grow = gumbel + ((size_t)step * NB + m) * (size_t)NV + bn;
        unsigned long long best = 0ull;
#pragma unroll
        for (int p = 0; p < 4; p++) {
            int nl = tx8 + 2 * p;
            int n = bn + nl;
            if (n + 1 < N) {
                float2 g = *(const float2*)(grow + nl);
                float v0 = lo32(acc[i][p]) + bo[nl] + g.x;
                float v1 = hi32(acc[i][p]) + bo[nl + 1] + g.y;
                unsigned long long p0 = packmax(v0, n);
                unsigned long long p1 = packmax(v1, n + 1);
                unsigned long long pm = p0 > p1 ? p0 : p1;
                if (pm > best) best = pm;
            } else if (n < N) {
                float v0 = lo32(acc[i][p]) + bo[nl] + grow[nl];
                unsigned long long p0 = packmax(v0, n);
                if (p0 > best) best = p0;
            }
        }
        atomicMax(&rowmax[ty8 + i], best);
    }
    __syncthreads();
    if (tid < 128 && rowmax[tid])
        atomicMax(&g_amax[bm + tid], rowmax[tid]);
}

// ---------------- finalize step: decode argmax, write one-hot, gather next x ----------------
__global__ void finalize_kernel(const float* __restrict__ emb, float* __restrict__ out, int s) {
    int b = blockIdx.x;
    __shared__ int stok;
    if (threadIdx.x == 0) {
        unsigned long long p = g_amax[b];
        int t = (int)(0xFFFFFFFFu - (unsigned)(p & 0xFFFFFFFFull));
        stok = t;
        g_tok[s * NB + b] = t;
        g_amax[b] = 0ull;
        out[((size_t)b * NS + s) * NV + t] = 1.0f;
    }
    __syncthreads();
    int t = stok;
    for (int k = threadIdx.x; k < DEMB; k += 128)
        g_x[b * DEMB + k] = fmaxf(emb[(size_t)t * DEMB + k], 0.f);
}

// ---------------- msg_lens: last EOS index + 1, else S ----------------
__global__ void lens_kernel(float* __restrict__ out, int out_size) {
    int b = threadIdx.x;
    int len = NS;
    for (int s = NS - 1; s >= 0; --s) {
        if (g_tok[s * NB + b] == EOS_TOK) { len = s + 1; break; }
    }
    if (out_size >= NB * NS * NV + NB)
        out[(size_t)NB * NS * NV + b] = (float)len;
}

// ---------------- launch ----------------
extern "C" void kernel_launch(void* const* d_in, const int* in_sizes, int n_in,
                              void* d_out, int out_size)
{
    const float* image = (const float*)d_in[0];
    const float* W_b   = (const float*)d_in[1];
    const float* emb   = (const float*)d_in[2];
    const float* w_ih  = (const float*)d_in[3];
    const float* w_hh  = (const float*)d_in[4];
    const float* b_ih  = (const float*)d_in[5];
    const float* b_hh  = (const float*)d_in[6];
    const float* W_out = (const float*)d_in[7];
    const float* b_out = (const float*)d_in[8];
    const float* gum   = (const float*)d_in[9];
    float* out = (float*)d_out;

    // zero the one-hot region
    long long n4 = (long long)NB * NS * NV / 4;
    zero_out<<<(unsigned)((n4 + 255) / 256), 256>>>((float4*)out, n4);

    // one-time prep
    transpose_wb<<<dim3(DIMG / 32, DHID / 32), dim3(32, 8)>>>(W_b);
    init_kernel<<<NB, 128>>>(emb);

    // h0 = image @ W_b  (A=image ext, B=g_WbT sel 5, C=g_h0 sel 0)
    gemm64_dual<<<dim3(DHID / 128, NB / 64, 1), 256>>>(
        -1, image, 5, nullptr, 0, DIMG,
        -1, nullptr, -1, nullptr, 0, 0,
        DHID);

    for (int s = 0; s < NS; ++s) {
        int hc = s & 1;       // current h buffer (h0 lives in buf 0)
        int hn = hc ^ 1;      // next h buffer
        // fused gate GEMMs: z=0 -> G1 = x @ w_ih^T (K=512); z=1 -> G2 = h @ w_hh^T (K=1024)
        gemm64_dual<<<dim3(3 * DHID / 128, NB / 64, 2), 256>>>(
            2, nullptr, -1, w_ih, 3, DEMB,
            hc, nullptr, -1, w_hh, 4, DHID,
            3 * DHID);
        gru_elem<<<(NB * DHID) / 256, 256>>>(b_ih, b_hh, hc, hn);
        gemm_logits<<<dim3((NV + 127) / 128, NB / 128), 256>>>(hn, W_out, b_out, gum, s);
        finalize_kernel<<<NB, 128>>>(emb, out, s);
    }

    lens_kernel<<<1, 256>>>(out, out_size);
}